// round 10
// baseline (speedup 1.0000x reference)
#include <cuda_runtime.h>
#include <cstdint>

// ---------------------------------------------------------------------------
// DynamicFixedQuantizer, R9: speculate-and-repair.
//  Kernel A: ONE pass -- quantize with speculative sigma=0.125 (the outcome
//    for any input where overflow<=r_max and underflow<r_max) while exactly
//    counting overflow/underflow vs the fixed sigma0=0.25 thresholds; last
//    CTA decides the true sigma into g_qp.
//  Kernel B: if true sigma != 0.125, requantize (never fires for data where
//    the speculation holds; exits in ~us otherwise). Correct for ALL inputs.
// ---------------------------------------------------------------------------

__device__ unsigned int g_over  = 0u;
__device__ unsigned int g_under = 0u;
__device__ unsigned int g_done  = 0u;
__device__ float4 g_qp;   // x=sigma, y=1/sigma

// Thresholds from sigma0 = 2^(6-8) = 0.25, bit=8, half=128:
#define T_MAX0   31.75f
#define T_MIN0  (-32.0f)
#define HT_MAX0  15.875f
#define HT_MIN0 (-16.0f)

#define SPEC_SIGMA 0.125f
#define SPEC_INV   8.0f

// --- integer add forced onto the fma pipe: IMAD d = a*one + b ---------------
__device__ __forceinline__ uint32_t addi(uint32_t a, uint32_t one, uint32_t b) {
    uint32_t d;
    asm("mad.lo.u32 %0, %1, %2, %3;" : "=r"(d) : "r"(a), "r"(one), "r"(b));
    return d;
}

// acc += (a > T)  as FSETP + predicated IMAD (both fma-pipe class).
__device__ __forceinline__ void cadd_gt(int& acc, float a, float T, uint32_t one) {
    asm("{\n\t.reg .pred p;\n\t"
        "setp.gt.f32 p, %1, %2;\n\t"
        "@p mad.lo.u32 %0, %3, 1, %0;\n\t}"
        : "+r"(acc) : "f"(a), "f"(T), "r"(one));
}
// acc += (a < T)
__device__ __forceinline__ void cadd_lt(int& acc, float a, float T, uint32_t one) {
    asm("{\n\t.reg .pred p;\n\t"
        "setp.lt.f32 p, %1, %2;\n\t"
        "@p mad.lo.u32 %0, %3, 1, %0;\n\t}"
        : "+r"(acc) : "f"(a), "f"(T), "r"(one));
}

// clip(floor(s), -128, 127) via saturating round-to-neg-inf conversion, then
// back to float. Bit-identical to clip(floor(s)*sigma, tmin, tmax)/sigma since
// sigma>0 is a power of two, tmin=-128*sigma, tmax=127*sigma.
__device__ __forceinline__ float floor_clip_s8(float s) {
    int   q;
    float r;
    asm("cvt.rmi.s8.f32 %0, %1;" : "=r"(q) : "f"(s));
    asm("cvt.rn.f32.s8 %0, %1;"  : "=f"(r) : "r"(q));
    return r;
}

// Round: IMAD add (fma) + SHF rotate (alu) + LOP3 xor (alu). Proven best.
#define TF_S(r) { x0 = addi(x0, one, x1); x1 = __funnelshift_l(x1, x1, (r)) ^ x0; }

#define TF_KEYS                                                               \
    const uint32_t ks2 = k0 ^ k1 ^ 0x1BD11BDAu;                               \
    const uint32_t kc1 = ks2 + 1u;                                            \
    const uint32_t kc2 = k0  + 2u;                                            \
    const uint32_t kc3 = k1  + 3u;                                            \
    const uint32_t kc4 = ks2 + 4u;                                            \
    const uint32_t kc5 = k0  + 5u;                                            \
    const uint32_t m23 = one << 23;

#define TF_BLOCK(JIDX)                                                        \
    uint32_t x0 = k0;                                                         \
    uint32_t x1 = addi((uint32_t)(JIDX), one, k1);                            \
    TF_S(13) TF_S(15) TF_S(26) TF_S(6)                                        \
    x0 = addi(x0, one, k1);  x1 = addi(x1, one, kc1);                         \
    TF_S(17) TF_S(29) TF_S(16) TF_S(24)                                       \
    x0 = addi(x0, one, ks2); x1 = addi(x1, one, kc2);                         \
    TF_S(13) TF_S(15) TF_S(26) TF_S(6)                                        \
    x0 = addi(x0, one, k0);  x1 = addi(x1, one, kc3);                         \
    TF_S(17) TF_S(29) TF_S(16) TF_S(24)                                       \
    x0 = addi(x0, one, k1);  x1 = addi(x1, one, kc4);                         \
    TF_S(13) TF_S(15) TF_S(26) TF_S(6)                                        \
    x0 = addi(x0, one, ks2); x1 = addi(x1, one, kc5);

__device__ __forceinline__ float tf_f(uint32_t bits, uint32_t m23) {
    // bits>>9 == mulhi(bits, 2^23): narrow IMAD.HI on the fma pipe.
    uint32_t hi;
    asm("mul.hi.u32 %0, %1, %2;" : "=r"(hi) : "r"(bits), "r"(m23));
    // float(hi)*2^-23 == bitcast(hi|0x3f800000)-1 exactly (hi < 2^23).
    return __uint2float_rn(hi);
}

// --- Kernel A: speculative quantize + exact count + decide ------------------
__global__ void __launch_bounds__(256) quantize_count_kernel(
        const float* __restrict__ x, float* __restrict__ out,
        uint32_t k0, uint32_t k1, uint32_t one, int n, float nf) {
    int t = blockIdx.x * blockDim.x + threadIdx.x;
    int j = t << 4;                 // 16 elements per thread
    int over = 0, under = 0;

    if (j < n) {
        TF_KEYS

        // Front-batched streaming loads (MLP=4).
        float4 v[4];
#pragma unroll
        for (int b = 0; b < 4; b++)
            v[b] = __ldcg(reinterpret_cast<const float4*>(x + j + 4 * b));

        // Exact counts vs sigma0 thresholds (fma-pipe FSETP + @p IMAD).
#pragma unroll
        for (int b = 0; b < 4; b++) {
#pragma unroll
            for (int c = 0; c < 4; c++) {
                float a = (&v[b].x)[c];
                cadd_gt(over,  a, T_MAX0,  one);
                cadd_lt(over,  a, T_MIN0,  one);
                cadd_gt(under, a, HT_MAX0, one);
                cadd_lt(under, a, HT_MIN0, one);
            }
        }

        // RNG: 16 independent threefry chains.
        float f[16];
#pragma unroll
        for (int c = 0; c < 16; c++) {
            TF_BLOCK(j + c)
            f[c] = tf_f(x0 ^ x1, m23);
        }

        // Speculative epilogue with sigma=0.125 as immediates.
#pragma unroll
        for (int b = 0; b < 4; b++) {
            float4 q;
#pragma unroll
            for (int c = 0; c < 4; c++) {
                float a = (&v[b].x)[c];
                // s = a*8 + f*2^-23 (bit-identical to the general form)
                float s = __fmaf_rn(f[4 * b + c], 1.1920928955078125e-7f,
                                    __fmul_rn(a, SPEC_INV));
                (&q.x)[c] = __fmul_rn(floor_clip_s8(s), SPEC_SIGMA);
            }
            __stcs(reinterpret_cast<float4*>(out + j + 4 * b), q);
        }
    }

    // Block reduce + global atomics + last-block decide (all threads join).
    over  = __reduce_add_sync(0xffffffffu, over);
    under = __reduce_add_sync(0xffffffffu, under);

    __shared__ int so[8], su[8];
    int warp = threadIdx.x >> 5;
    int lane = threadIdx.x & 31;
    if (lane == 0) { so[warp] = over; su[warp] = under; }
    __syncthreads();

    if (threadIdx.x == 0) {
        int o = 0, u = 0;
#pragma unroll
        for (int w = 0; w < 8; w++) { o += so[w]; u += su[w]; }
        atomicAdd(&g_over,  (unsigned)o);
        atomicAdd(&g_under, (unsigned)u);
        __threadfence();
        unsigned tk = atomicAdd(&g_done, 1u);
        if (tk == gridDim.x - 1) {
            unsigned ov = atomicAdd(&g_over,  0u);
            unsigned un = atomicAdd(&g_under, 0u);
            float overflow  = __uint2float_rn(ov) / nf;
            float underflow = __uint2float_rn(un) / nf;
            float sigma = 0.25f;
            if (overflow > 0.01f)       sigma = 0.5f;
            else if (underflow < 0.01f) sigma = 0.125f;
            g_qp = make_float4(sigma, 1.0f / sigma, 0.0f, 0.0f);
            atomicExch(&g_over,  0u);
            atomicExch(&g_under, 0u);
            __threadfence();
            atomicExch(&g_done,  0u);
        }
    }
}

// --- Kernel B: repair pass (no-op when speculation held) --------------------
__global__ void __launch_bounds__(256) repair_kernel(
        const float* __restrict__ x, float* __restrict__ out,
        uint32_t k0, uint32_t k1, uint32_t one, int n) {
    float4 qp = g_qp;             // x=sigma, y=inv
    if (qp.x == SPEC_SIGMA) return;   // speculation was correct -> done

    TF_KEYS
    int tid    = blockIdx.x * blockDim.x + threadIdx.x;
    int stride = gridDim.x * blockDim.x;
    int ntile  = n >> 4;

    for (int tile = tid; tile < ntile; tile += stride) {
        int j = tile << 4;
        float4 v[4];
#pragma unroll
        for (int b = 0; b < 4; b++)
            v[b] = __ldcg(reinterpret_cast<const float4*>(x + j + 4 * b));

        float f[16];
#pragma unroll
        for (int c = 0; c < 16; c++) {
            TF_BLOCK(j + c)
            f[c] = tf_f(x0 ^ x1, m23);
        }

#pragma unroll
        for (int b = 0; b < 4; b++) {
            float4 q;
#pragma unroll
            for (int c = 0; c < 4; c++) {
                float a = (&v[b].x)[c];
                float s = __fmaf_rn(f[4 * b + c], 1.1920928955078125e-7f,
                                    __fmul_rn(a, qp.y));
                (&q.x)[c] = __fmul_rn(floor_clip_s8(s), qp.x);
            }
            __stcs(reinterpret_cast<float4*>(out + j + 4 * b), q);
        }
    }
}

// --- host-side threefry for key fold ---------------------------------------
static void h_threefry(uint32_t k0, uint32_t k1, uint32_t x0, uint32_t x1,
                       uint32_t& o0, uint32_t& o1) {
    auto rotl = [](uint32_t v, int r) { return (v << r) | (v >> (32 - r)); };
    uint32_t ks[3] = { k0, k1, k0 ^ k1 ^ 0x1BD11BDAu };
    const int R[2][4] = { {13, 15, 26, 6}, {17, 29, 16, 24} };
    x0 += ks[0]; x1 += ks[1];
    for (int i = 0; i < 5; i++) {
        for (int jj = 0; jj < 4; jj++) {
            x0 += x1; x1 = rotl(x1, R[i % 2][jj]); x1 ^= x0;
        }
        x0 += ks[(i + 1) % 3];
        x1 += ks[(i + 2) % 3] + (uint32_t)(i + 1);
    }
    o0 = x0; o1 = x1;
}

extern "C" void kernel_launch(void* const* d_in, const int* in_sizes, int n_in,
                              void* d_out, int out_size) {
    const float* x = (const float*)d_in[0];
    float* out = (float*)d_out;
    int n = in_sizes[0];           // 32*2048*2048 = 134217728

    // key = fold_in(key(42), 0): threefry_2x32(key=[0,42], count=[0,0])
    uint32_t fk0, fk1;
    h_threefry(0u, 42u, 0u, 0u, fk0, fk1);

    int qthreads = (n + 15) >> 4;  // 16 elements per thread
    int qblocks = (qthreads + 255) / 256;
    quantize_count_kernel<<<qblocks, 256>>>(x, out, fk0, fk1, 1u, n, (float)n);

    // Repair: no-op unless true sigma != 0.125 (exits in a few us).
    repair_kernel<<<1184, 256>>>(x, out, fk0, fk1, 1u, n);
}

// round 12
// speedup vs baseline: 1.0068x; 1.0068x over previous
#include <cuda_runtime.h>
#include <cstdint>

// ---------------------------------------------------------------------------
// DynamicFixedQuantizer, R11 (= R10 + OR-fused counters):
//  Kernel A: ONE pass -- quantize with speculative sigma=0.125 while exactly
//    counting overflow/underflow vs fixed sigma0=0.25 thresholds; each
//    counter is FSETP + FSETP.OR + @p IMAD (3 fma ops, was 4); last CTA
//    decides the true sigma into g_qp.
//  Kernel B: repair pass, no-op when speculation held (any-input correct).
// ---------------------------------------------------------------------------

__device__ unsigned int g_over  = 0u;
__device__ unsigned int g_under = 0u;
__device__ unsigned int g_done  = 0u;
__device__ float4 g_qp;   // x=sigma, y=1/sigma

// Thresholds from sigma0 = 2^(6-8) = 0.25, bit=8, half=128:
#define T_MAX0   31.75f
#define T_MIN0  (-32.0f)
#define HT_MAX0  15.875f
#define HT_MIN0 (-16.0f)

#define SPEC_SIGMA 0.125f
#define SPEC_INV   8.0f

// --- integer add forced onto the fma pipe: IMAD d = a*one + b ---------------
__device__ __forceinline__ uint32_t addi(uint32_t a, uint32_t one, uint32_t b) {
    uint32_t d;
    asm("mad.lo.u32 %0, %1, %2, %3;" : "=r"(d) : "r"(a), "r"(one), "r"(b));
    return d;
}

// acc += (a > Tmax) || (a < Tmin)   -- conditions disjoint, so OR == sum.
// FSETP.lt + FSETP.gt.OR + predicated IMAD: 3 fma-class ops (was 4).
// NaN: both compares false -> no count (matches jnp semantics).
__device__ __forceinline__ void cadd_range(int& acc, float a,
                                           float Tmax, float Tmin,
                                           uint32_t one) {
    asm("{\n\t.reg .pred p, q;\n\t"
        "setp.lt.f32 q, %1, %3;\n\t"
        "setp.gt.or.f32 p, %1, %2, q;\n\t"
        "@p mad.lo.u32 %0, %4, 1, %0;\n\t}"
        : "+r"(acc) : "f"(a), "f"(Tmax), "f"(Tmin), "r"(one));
}

// clip(floor(s), -128, 127) via saturating round-to-neg-inf conversion, then
// back to float. Bit-identical to clip(floor(s)*sigma, tmin, tmax)/sigma since
// sigma>0 is a power of two, tmin=-128*sigma, tmax=127*sigma.
__device__ __forceinline__ float floor_clip_s8(float s) {
    int   q;
    float r;
    asm("cvt.rmi.s8.f32 %0, %1;" : "=r"(q) : "f"(s));
    asm("cvt.rn.f32.s8 %0, %1;"  : "=f"(r) : "r"(q));
    return r;
}

// Round: IMAD add (fma) + SHF rotate (alu) + LOP3 xor (alu). Proven best.
#define TF_S(r) { x0 = addi(x0, one, x1); x1 = __funnelshift_l(x1, x1, (r)) ^ x0; }

#define TF_KEYS                                                               \
    const uint32_t ks2 = k0 ^ k1 ^ 0x1BD11BDAu;                               \
    const uint32_t kc1 = ks2 + 1u;                                            \
    const uint32_t kc2 = k0  + 2u;                                            \
    const uint32_t kc3 = k1  + 3u;                                            \
    const uint32_t kc4 = ks2 + 4u;                                            \
    const uint32_t kc5 = k0  + 5u;                                            \
    const uint32_t m23 = one << 23;

#define TF_BLOCK(JIDX)                                                        \
    uint32_t x0 = k0;                                                         \
    uint32_t x1 = addi((uint32_t)(JIDX), one, k1);                            \
    TF_S(13) TF_S(15) TF_S(26) TF_S(6)                                        \
    x0 = addi(x0, one, k1);  x1 = addi(x1, one, kc1);                         \
    TF_S(17) TF_S(29) TF_S(16) TF_S(24)                                       \
    x0 = addi(x0, one, ks2); x1 = addi(x1, one, kc2);                         \
    TF_S(13) TF_S(15) TF_S(26) TF_S(6)                                        \
    x0 = addi(x0, one, k0);  x1 = addi(x1, one, kc3);                         \
    TF_S(17) TF_S(29) TF_S(16) TF_S(24)                                       \
    x0 = addi(x0, one, k1);  x1 = addi(x1, one, kc4);                         \
    TF_S(13) TF_S(15) TF_S(26) TF_S(6)                                        \
    x0 = addi(x0, one, ks2); x1 = addi(x1, one, kc5);

__device__ __forceinline__ float tf_f(uint32_t bits, uint32_t m23) {
    // bits>>9 == mulhi(bits, 2^23): narrow IMAD.HI on the fma pipe.
    uint32_t hi;
    asm("mul.hi.u32 %0, %1, %2;" : "=r"(hi) : "r"(bits), "r"(m23));
    // float(hi)*2^-23 == bitcast(hi|0x3f800000)-1 exactly (hi < 2^23).
    return __uint2float_rn(hi);
}

// --- Kernel A: speculative quantize + exact count + decide ------------------
__global__ void __launch_bounds__(256) quantize_count_kernel(
        const float* __restrict__ x, float* __restrict__ out,
        uint32_t k0, uint32_t k1, uint32_t one, int n, float nf) {
    int t = blockIdx.x * blockDim.x + threadIdx.x;
    int j = t << 4;                 // 16 elements per thread
    int over = 0, under = 0;

    if (j < n) {
        TF_KEYS

        // Front-batched streaming loads (MLP=4).
        float4 v[4];
#pragma unroll
        for (int b = 0; b < 4; b++)
            v[b] = __ldcg(reinterpret_cast<const float4*>(x + j + 4 * b));

        // Exact counts vs sigma0 thresholds (OR-fused, 3 fma ops per counter).
#pragma unroll
        for (int b = 0; b < 4; b++) {
#pragma unroll
            for (int c = 0; c < 4; c++) {
                float a = (&v[b].x)[c];
                cadd_range(over,  a, T_MAX0,  T_MIN0,  one);
                cadd_range(under, a, HT_MAX0, HT_MIN0, one);
            }
        }

        // RNG: 16 independent threefry chains.
        float f[16];
#pragma unroll
        for (int c = 0; c < 16; c++) {
            TF_BLOCK(j + c)
            f[c] = tf_f(x0 ^ x1, m23);
        }

        // Speculative epilogue with sigma=0.125 as immediates.
#pragma unroll
        for (int b = 0; b < 4; b++) {
            float4 q;
#pragma unroll
            for (int c = 0; c < 4; c++) {
                float a = (&v[b].x)[c];
                // s = a*8 + f*2^-23 (both products exact -> bit-identical)
                float s = __fmaf_rn(f[4 * b + c], 1.1920928955078125e-7f,
                                    __fmul_rn(a, SPEC_INV));
                (&q.x)[c] = __fmul_rn(floor_clip_s8(s), SPEC_SIGMA);
            }
            __stcs(reinterpret_cast<float4*>(out + j + 4 * b), q);
        }
    }

    // Block reduce + global atomics + last-block decide (all threads join).
    over  = __reduce_add_sync(0xffffffffu, over);
    under = __reduce_add_sync(0xffffffffu, under);

    __shared__ int so[8], su[8];
    int warp = threadIdx.x >> 5;
    int lane = threadIdx.x & 31;
    if (lane == 0) { so[warp] = over; su[warp] = under; }
    __syncthreads();

    if (threadIdx.x == 0) {
        int o = 0, u = 0;
#pragma unroll
        for (int w = 0; w < 8; w++) { o += so[w]; u += su[w]; }
        atomicAdd(&g_over,  (unsigned)o);
        atomicAdd(&g_under, (unsigned)u);
        __threadfence();
        unsigned tk = atomicAdd(&g_done, 1u);
        if (tk == gridDim.x - 1) {
            unsigned ov = atomicAdd(&g_over,  0u);
            unsigned un = atomicAdd(&g_under, 0u);
            float overflow  = __uint2float_rn(ov) / nf;
            float underflow = __uint2float_rn(un) / nf;
            float sigma = 0.25f;
            if (overflow > 0.01f)       sigma = 0.5f;
            else if (underflow < 0.01f) sigma = 0.125f;
            g_qp = make_float4(sigma, 1.0f / sigma, 0.0f, 0.0f);
            atomicExch(&g_over,  0u);
            atomicExch(&g_under, 0u);
            __threadfence();
            atomicExch(&g_done,  0u);
        }
    }
}

// --- Kernel B: repair pass (no-op when speculation held) --------------------
__global__ void __launch_bounds__(256) repair_kernel(
        const float* __restrict__ x, float* __restrict__ out,
        uint32_t k0, uint32_t k1, uint32_t one, int n) {
    float4 qp = g_qp;             // x=sigma, y=inv
    if (qp.x == SPEC_SIGMA) return;   // speculation was correct -> done

    TF_KEYS
    int tid    = blockIdx.x * blockDim.x + threadIdx.x;
    int stride = gridDim.x * blockDim.x;
    int ntile  = n >> 4;

    for (int tile = tid; tile < ntile; tile += stride) {
        int j = tile << 4;
        float4 v[4];
#pragma unroll
        for (int b = 0; b < 4; b++)
            v[b] = __ldcg(reinterpret_cast<const float4*>(x + j + 4 * b));

        float f[16];
#pragma unroll
        for (int c = 0; c < 16; c++) {
            TF_BLOCK(j + c)
            f[c] = tf_f(x0 ^ x1, m23);
        }

#pragma unroll
        for (int b = 0; b < 4; b++) {
            float4 q;
#pragma unroll
            for (int c = 0; c < 4; c++) {
                float a = (&v[b].x)[c];
                float s = __fmaf_rn(f[4 * b + c], 1.1920928955078125e-7f,
                                    __fmul_rn(a, qp.y));
                (&q.x)[c] = __fmul_rn(floor_clip_s8(s), qp.x);
            }
            __stcs(reinterpret_cast<float4*>(out + j + 4 * b), q);
        }
    }
}

// --- host-side threefry for key fold ---------------------------------------
static void h_threefry(uint32_t k0, uint32_t k1, uint32_t x0, uint32_t x1,
                       uint32_t& o0, uint32_t& o1) {
    auto rotl = [](uint32_t v, int r) { return (v << r) | (v >> (32 - r)); };
    uint32_t ks[3] = { k0, k1, k0 ^ k1 ^ 0x1BD11BDAu };
    const int R[2][4] = { {13, 15, 26, 6}, {17, 29, 16, 24} };
    x0 += ks[0]; x1 += ks[1];
    for (int i = 0; i < 5; i++) {
        for (int jj = 0; jj < 4; jj++) {
            x0 += x1; x1 = rotl(x1, R[i % 2][jj]); x1 ^= x0;
        }
        x0 += ks[(i + 1) % 3];
        x1 += ks[(i + 2) % 3] + (uint32_t)(i + 1);
    }
    o0 = x0; o1 = x1;
}

extern "C" void kernel_launch(void* const* d_in, const int* in_sizes, int n_in,
                              void* d_out, int out_size) {
    const float* x = (const float*)d_in[0];
    float* out = (float*)d_out;
    int n = in_sizes[0];           // 32*2048*2048 = 134217728

    // key = fold_in(key(42), 0): threefry_2x32(key=[0,42], count=[0,0])
    uint32_t fk0, fk1;
    h_threefry(0u, 42u, 0u, 0u, fk0, fk1);

    int qthreads = (n + 15) >> 4;  // 16 elements per thread
    int qblocks = (qthreads + 255) / 256;
    quantize_count_kernel<<<qblocks, 256>>>(x, out, fk0, fk1, 1u, n, (float)n);

    // Repair: no-op unless true sigma != 0.125 (exits in a few us).
    repair_kernel<<<1184, 256>>>(x, out, fk0, fk1, 1u, n);
}